// round 3
// baseline (speedup 1.0000x reference)
#include <cuda_runtime.h>
#include <cuda_bf16.h>
#include <math.h>

#define T_LEN   16384
#define C_CH    8
#define W_WIN   256
#define R_OUT   32
#define TILE_T  1024
#define NFILT   256          // C*R
#define PI_D    3.14159265358979323846

// Precomputed Gabor bank, transposed: g_gaborT[w*256 + fidx] = (fr, fi)
__device__ float2 g_gaborT[W_WIN * NFILT];

// ---------------------------------------------------------------------------
// f32x2 packed helpers
// ---------------------------------------------------------------------------
__device__ __forceinline__ unsigned long long fma2(unsigned long long a,
                                                   unsigned long long b,
                                                   unsigned long long c) {
    unsigned long long d;
    asm("fma.rn.f32x2 %0, %1, %2, %3;" : "=l"(d) : "l"(a), "l"(b), "l"(c));
    return d;
}
__device__ __forceinline__ unsigned long long pack_dup(float x) {
    unsigned long long d;
    asm("mov.b64 %0, {%1, %1};" : "=l"(d) : "f"(x));
    return d;
}
__device__ __forceinline__ unsigned long long pack2(float lo, float hi) {
    unsigned long long d;
    asm("mov.b64 %0, {%1, %2};" : "=l"(d) : "f"(lo), "f"(hi));
    return d;
}
__device__ __forceinline__ void unpack2(unsigned long long v, float& lo, float& hi) {
    asm("mov.b64 {%0, %1}, %2;" : "=f"(lo), "=f"(hi) : "l"(v));
}

// ---------------------------------------------------------------------------
// Filter-bank precompute: matches reference fp32 rounding of the phase/gauss
// arguments, with accurate (double) cos/sin/exp evaluation of those fp32 args.
// ---------------------------------------------------------------------------
__global__ void gabor_precompute_kernel(const float* __restrict__ kV,
                                        const float* __restrict__ sV) {
    int idx = blockIdx.x * blockDim.x + threadIdx.x;   // 65536 = 256 w * 256 f
    if (idx >= W_WIN * NFILT) return;
    int w = idx >> 8;          // tap
    int f = idx & 255;         // filter index
    float k = kV[f];
    float s = sV[f];

    const float c0 = (float)(-2.0 * PI_D / (double)W_WIN);
    float a   = __fmul_rn(c0, k);
    float ph  = __fmul_rn(a, (float)w);

    float nm      = (float)w - 128.0f;                    // n - mu
    float inv2s2  = 1.0f / (2.0f * s * s);
    float coef    = 1.0f / sqrtf(2.0f * (float)PI_D * s * s);
    float arg     = __fmul_rn(inv2s2, __fmul_rn(nm, nm));
    float g       = __fmul_rn(coef, (float)exp(-(double)arg));

    float fr = __fmul_rn((float)cos((double)ph), g);
    float fi = __fmul_rn((float)sin((double)ph), g);
    g_gaborT[idx] = make_float2(fr, fi);
}

// ---------------------------------------------------------------------------
// Main kernel. Block = (tile, c, b). 256 threads = 8 warps.
// lane = filter j within channel (writes output r = 31 - j).
// Each warp processes 8 consecutive t per chunk with a rotating packed-x
// register window; accumulators are packed (cos,sin) f32x2.
// ---------------------------------------------------------------------------
__global__ void __launch_bounds__(256, 3)
wavelet_main_kernel(const float* __restrict__ x, float* __restrict__ out) {
    extern __shared__ unsigned char smem[];
    unsigned long long* f_sh = (unsigned long long*)smem;                // 8192 * 8B
    float* x_sh = (float*)(smem + (size_t)W_WIN * R_OUT * 8);            // 1280 * 4B

    const int tile = blockIdx.x;
    const int c    = blockIdx.y;
    const int b    = blockIdx.z;
    const int t0   = tile * TILE_T;
    const int tid  = threadIdx.x;

    // Load this channel's 32 filters into shared: f_sh[w*32 + j].
    // Global reads coalesced (j-major within a warp? -> idx: w = idx>>5, j = idx&31
    // gives warp spanning one w, 32 consecutive filters = 256B). STS consecutive.
    for (int idx = tid; idx < W_WIN * R_OUT; idx += 256) {
        int w = idx >> 5;
        int j = idx & 31;
        float2 v = g_gaborT[w * NFILT + c * R_OUT + j];
        f_sh[idx] = pack2(v.x, v.y);
    }

    // Load x window: x_sh[j] = x[b, t0 - 128 + j, c], zero-padded.
    for (int j = tid; j < TILE_T + 256; j += 256) {
        int t = t0 - 128 + j;
        float v = 0.0f;
        if (t >= 0 && t < T_LEN)
            v = x[((size_t)b * T_LEN + t) * C_CH + c];
        x_sh[j] = v;
    }
    __syncthreads();

    const int wi   = tid >> 5;
    const int lane = tid & 31;

    for (int ch = wi; ch < TILE_T / 8; ch += 8) {
        const int toff = ch * 8;

        unsigned long long acc[8];
        unsigned long long xp[8];
#pragma unroll
        for (int i = 0; i < 8; i++) acc[i] = 0ull;
#pragma unroll
        for (int i = 0; i < 8; i++) xp[i] = pack_dup(x_sh[toff + i]);

        for (int w0 = 0; w0 < W_WIN; w0 += 8) {
#pragma unroll
            for (int u = 0; u < 8; u++) {
                const int w = w0 + u;
                unsigned long long f2 = f_sh[w * 32 + lane];
#pragma unroll
                for (int i = 0; i < 8; i++)
                    acc[i] = fma2(xp[(u + i) & 7], f2, acc[i]);
                // slot u now holds tap index w+8 ( (w+8) & 7 == u )
                xp[u] = pack_dup(x_sh[toff + w + 8]);
            }
        }

        // power = cr^2 + ci^2 ; write out[b, t, c*32 + (31-lane)]
        const int rout = 31 - lane;
#pragma unroll
        for (int i = 0; i < 8; i++) {
            float cr, ci;
            unpack2(acc[i], cr, ci);
            float p = cr * cr + ci * ci;
            int t = t0 + toff + i;
            out[((size_t)b * T_LEN + t) * (C_CH * R_OUT) + c * R_OUT + rout] = p;
        }
    }
}

// ---------------------------------------------------------------------------
// Launch
// ---------------------------------------------------------------------------
extern "C" void kernel_launch(void* const* d_in, const int* in_sizes, int n_in,
                              void* d_out, int out_size) {
    const float* x  = (const float*)d_in[0];
    const float* kV = (const float*)d_in[1];
    const float* sV = (const float*)d_in[2];
    float* out = (float*)d_out;

    const int B = in_sizes[0] / (T_LEN * C_CH);   // D = 1

    // Filter bank (cheap; runs inside the graph each replay, deterministic)
    gabor_precompute_kernel<<<(W_WIN * NFILT + 255) / 256, 256>>>(kV, sV);

    const size_t smem_bytes = (size_t)W_WIN * R_OUT * 8 + (TILE_T + 256) * 4;
    static bool attr_set = false;
    if (!attr_set) {
        cudaFuncSetAttribute(wavelet_main_kernel,
                             cudaFuncAttributeMaxDynamicSharedMemorySize,
                             (int)smem_bytes);
        attr_set = true;
    }

    dim3 grid(T_LEN / TILE_T, C_CH, B);
    wavelet_main_kernel<<<grid, 256, smem_bytes>>>(x, out);
}

// round 9
// speedup vs baseline: 2.7804x; 2.7804x over previous
#include <cuda_runtime.h>
#include <cuda_bf16.h>
#include <math.h>
#include <stdint.h>

#define T_LEN    16384
#define C_CH     8
#define W_WIN    256
#define R_OUT    32
#define NFILT    256
#define ROWS_CTA 256
#define PI_D     3.14159265358979323846

// Gabor banks pre-laid-out in m16n8k16 B-fragment order:
// u32 index = ((((c*2+bank)*16 + q)*4 + i4)*32 + lane)*4 + reg
// bank0 = bf16 main term, bank1 = bf16 residual. 512 KB total, L2-resident.
__device__ uint32_t g_bfrag[131072];

// ---------------------------------------------------------------------------
// helpers
// ---------------------------------------------------------------------------
__device__ __forceinline__ uint32_t cvt_bf16x2(float hi, float lo) {
    uint32_t d;
    asm("cvt.rn.satfinite.bf16x2.f32 %0, %1, %2;" : "=r"(d) : "f"(hi), "f"(lo));
    return d;
}

__device__ __forceinline__ void mma_bf16(float* c, const uint32_t* a,
                                         uint32_t b0, uint32_t b1) {
    asm volatile(
        "mma.sync.aligned.m16n8k16.row.col.f32.bf16.bf16.f32 "
        "{%0,%1,%2,%3}, {%4,%5,%6,%7}, {%8,%9}, {%0,%1,%2,%3};"
        : "+f"(c[0]), "+f"(c[1]), "+f"(c[2]), "+f"(c[3])
        : "r"(a[0]), "r"(a[1]), "r"(a[2]), "r"(a[3]), "r"(b0), "r"(b1));
}

// Build A fragment pair (main + residual) for diagonal s.
// A[m,k] = x_sh[m+k]; fragment depends only on s = mt + q.
__device__ __forceinline__ void build_frag(const float* __restrict__ x_sh,
                                           int base, int ko,
                                           uint32_t* A1, uint32_t* A2) {
#pragma unroll
    for (int v = 0; v < 2; v++) {
#pragma unroll
        for (int u = 0; u < 2; u++) {
            int j = base + 8 * u + ko + 8 * v;
            float lo = x_sh[j];
            float hi = x_sh[j + 1];
            uint32_t p1 = cvt_bf16x2(hi, lo);
            float rlo = lo - __uint_as_float(p1 << 16);
            float rhi = hi - __uint_as_float(p1 & 0xFFFF0000u);
            uint32_t p2 = cvt_bf16x2(rhi, rlo);
            int r = v * 2 + u;          // a0=(u0,v0) a1=(u1,v0) a2=(u0,v1) a3=(u1,v1)
            A1[r] = p1;
            A2[r] = p2;
        }
    }
}

// ---------------------------------------------------------------------------
// Precompute: fp32 Gabor bank (reference-rounding-matched), bf16-split,
// scattered directly into B-fragment layout.
// ---------------------------------------------------------------------------
__global__ void gabor_precompute_kernel(const float* __restrict__ kV,
                                        const float* __restrict__ sV) {
    int idx = blockIdx.x * blockDim.x + threadIdx.x;    // 65536 = w*256 + f
    if (idx >= W_WIN * NFILT) return;
    int w = idx >> 8;
    int f = idx & 255;
    float k = kV[f];
    float s = sV[f];

    const float c0 = (float)(-2.0 * PI_D / (double)W_WIN);
    float a  = __fmul_rn(c0, k);
    float ph = __fmul_rn(a, (float)w);

    float nm     = (float)w - 128.0f;
    float inv2s2 = 1.0f / (2.0f * s * s);
    float coef   = 1.0f / sqrtf(2.0f * (float)PI_D * s * s);
    float arg    = __fmul_rn(inv2s2, __fmul_rn(nm, nm));
    float g      = __fmul_rn(coef, (float)exp(-(double)arg));

    float fr = __fmul_rn((float)cos((double)ph), g);
    float fi = __fmul_rn((float)sin((double)ph), g);

    int c = f >> 5, j = f & 31;
    int q = w >> 4, kk = w & 15;
    __nv_bfloat16* bh = (__nv_bfloat16*)g_bfrag;

#pragma unroll
    for (int im = 0; im < 2; im++) {
        float val = im ? fi : fr;
        __nv_bfloat16 v1 = __float2bfloat16(val);
        __nv_bfloat16 v2 = __float2bfloat16(val - __bfloat162float(v1));
        int n    = 2 * j + im;
        int nt   = n >> 3;
        int lane = ((n & 7) << 2) | ((kk >> 1) & 3);
        int i4   = nt >> 1;
        int reg  = ((nt & 1) << 1) | (kk >> 3);
        int half = kk & 1;
#pragma unroll
        for (int bank = 0; bank < 2; bank++) {
            int u32i = ((((c * 2 + bank) * 16 + q) * 4 + i4) * 32 + lane) * 4 + reg;
            bh[u32i * 2 + half] = bank ? v2 : v1;
        }
    }
}

// ---------------------------------------------------------------------------
// Main kernel: CTA = 256 t-rows of one (b,c). 8 warps, warp tile m32 x n64.
// SMEM: B frags (2 banks x 32KB) | x window (512 f)
// ---------------------------------------------------------------------------
#define OFF_XS   65536
#define SMEM_TOT (65536 + 2048)

__global__ void __launch_bounds__(256, 2)
wavelet_mma_kernel(const float* __restrict__ x, float* __restrict__ out) {
    extern __shared__ unsigned char smem[];
    const uint4* __restrict__ bsm = (const uint4*)smem;          // uint4 idx = ((bank*16+q)*4+i4)*32 + lane
    float* x_sh = (float*)(smem + OFF_XS);

    const int tid  = threadIdx.x;
    const int wi   = tid >> 5;
    const int lane = tid & 31;
    const int c    = blockIdx.y;
    const int b    = blockIdx.z;
    const int t0   = blockIdx.x * ROWS_CTA;

    // Copy this channel's fragment banks (16384 u32 = 4096 uint4), coalesced.
    {
        const uint4* src = (const uint4*)(g_bfrag + c * 16384);
        uint4* dst = (uint4*)smem;
#pragma unroll
        for (int i = 0; i < 16; i++)
            dst[tid + i * 256] = src[tid + i * 256];
    }

    // x window: x_sh[j] = x[b, t0-128+j, c], zero-padded. 511 used.
    for (int j = tid; j < 512; j += 256) {
        int t = t0 - 128 + j;
        float v = 0.0f;
        if (t >= 0 && t < T_LEN)
            v = x[((size_t)b * T_LEN + t) * C_CH + c];
        x_sh[j] = v;
    }
    __syncthreads();

    float acc[2][8][4];
#pragma unroll
    for (int mt = 0; mt < 2; mt++)
#pragma unroll
        for (int nt = 0; nt < 8; nt++)
#pragma unroll
            for (int r = 0; r < 4; r++) acc[mt][nt][r] = 0.0f;

    const int base0 = wi * 32 + (lane >> 2);
    const int ko    = (lane & 3) * 2;

    uint32_t A1p[4], A2p[4], A1n[4], A2n[4];
    build_frag(x_sh, base0, ko, A1p, A2p);

#pragma unroll 4
    for (int q = 0; q < 16; q++) {
        build_frag(x_sh, base0 + (q + 1) * 16, ko, A1n, A2n);

        uint32_t bb[16];
        // bank 0: passes a1*b1 and a2*b1
#pragma unroll
        for (int i4 = 0; i4 < 4; i4++)
            *(uint4*)(bb + i4 * 4) = bsm[(q * 4 + i4) * 32 + lane];
#pragma unroll
        for (int nt = 0; nt < 8; nt++) {
            uint32_t b0 = bb[(nt >> 1) * 4 + (nt & 1) * 2];
            uint32_t b1 = bb[(nt >> 1) * 4 + (nt & 1) * 2 + 1];
            mma_bf16(acc[0][nt], A1p, b0, b1);
            mma_bf16(acc[1][nt], A1n, b0, b1);
            mma_bf16(acc[0][nt], A2p, b0, b1);
            mma_bf16(acc[1][nt], A2n, b0, b1);
        }
        // bank 1: pass a1*b2
#pragma unroll
        for (int i4 = 0; i4 < 4; i4++)
            *(uint4*)(bb + i4 * 4) = bsm[((16 + q) * 4 + i4) * 32 + lane];
#pragma unroll
        for (int nt = 0; nt < 8; nt++) {
            uint32_t b0 = bb[(nt >> 1) * 4 + (nt & 1) * 2];
            uint32_t b1 = bb[(nt >> 1) * 4 + (nt & 1) * 2 + 1];
            mma_bf16(acc[0][nt], A1p, b0, b1);
            mma_bf16(acc[1][nt], A1n, b0, b1);
        }

#pragma unroll
        for (int r = 0; r < 4; r++) {
            A1p[r] = A1n[r];
            A2p[r] = A2n[r];
        }
    }

    // Epilogue: power = re^2 + im^2 (re/im are the c0/c1 pair of each frag)
#pragma unroll
    for (int mt = 0; mt < 2; mt++) {
#pragma unroll
        for (int u = 0; u < 2; u++) {
            int t = t0 + wi * 32 + mt * 16 + (lane >> 2) + 8 * u;
            size_t ob = ((size_t)b * T_LEN + t) * (size_t)(C_CH * R_OUT) + c * R_OUT;
#pragma unroll
            for (int nt = 0; nt < 8; nt++) {
                float re = acc[mt][nt][2 * u];
                float im = acc[mt][nt][2 * u + 1];
                float p = re * re + im * im;
                int jj = nt * 4 + (lane & 3);
                out[ob + 31 - jj] = p;
            }
        }
    }
}

// ---------------------------------------------------------------------------
// Launch
// ---------------------------------------------------------------------------
extern "C" void kernel_launch(void* const* d_in, const int* in_sizes, int n_in,
                              void* d_out, int out_size) {
    const float* x  = (const float*)d_in[0];
    const float* kV = (const float*)d_in[1];
    const float* sV = (const float*)d_in[2];
    float* out = (float*)d_out;

    const int B = in_sizes[0] / (T_LEN * C_CH);

    gabor_precompute_kernel<<<(W_WIN * NFILT + 255) / 256, 256>>>(kV, sV);

    static bool attr_set = false;
    if (!attr_set) {
        cudaFuncSetAttribute(wavelet_mma_kernel,
                             cudaFuncAttributeMaxDynamicSharedMemorySize, SMEM_TOT);
        attr_set = true;
    }

    dim3 grid(T_LEN / ROWS_CTA, C_CH, B);
    wavelet_mma_kernel<<<grid, 256, SMEM_TOT>>>(x, out);
}

// round 10
// speedup vs baseline: 3.5348x; 1.2713x over previous
#include <cuda_runtime.h>
#include <cuda_fp16.h>
#include <math.h>
#include <stdint.h>

#define T_LEN    16384
#define C_CH     8
#define W_WIN    256
#define R_OUT    32
#define NFILT    256
#define ROWS_CTA 1024
#define BLK_ROWS 256
#define PI_D     3.14159265358979323846

// Gabor bank (fp16) pre-laid-out in m16n8k16 B-fragment order:
// u32 index = (((c*16 + q)*4 + i4)*32 + lane)*4 + reg   (256 KB, L2-resident)
__device__ uint32_t g_bfrag[65536];

// ---------------------------------------------------------------------------
// helpers
// ---------------------------------------------------------------------------
__device__ __forceinline__ uint32_t cvt_f16x2(float hi, float lo) {
    uint32_t d;
    asm("cvt.rn.f16x2.f32 %0, %1, %2;" : "=r"(d) : "f"(hi), "f"(lo));
    return d;
}
__device__ __forceinline__ void unpack_f16x2(uint32_t v, float& lo, float& hi) {
    asm("{ .reg .f16 l, h;\n\t"
        "  mov.b32 {l, h}, %2;\n\t"
        "  cvt.f32.f16 %0, l;\n\t"
        "  cvt.f32.f16 %1, h; }"
        : "=f"(lo), "=f"(hi) : "r"(v));
}

__device__ __forceinline__ void mma_f16(float* c, const uint32_t* a,
                                        uint32_t b0, uint32_t b1) {
    asm volatile(
        "mma.sync.aligned.m16n8k16.row.col.f32.f16.f16.f32 "
        "{%0,%1,%2,%3}, {%4,%5,%6,%7}, {%8,%9}, {%0,%1,%2,%3};"
        : "+f"(c[0]), "+f"(c[1]), "+f"(c[2]), "+f"(c[3])
        : "r"(a[0]), "r"(a[1]), "r"(a[2]), "r"(a[3]), "r"(b0), "r"(b1));
}

// Build A fragment pair (fp16 main + fp16 residual) for diagonal s.
// A[m,k] = x_sh[m+k]; fragment depends only on s = mt + q.
__device__ __forceinline__ void build_frag(const float* __restrict__ x_sh,
                                           int base, int ko,
                                           uint32_t* A1, uint32_t* A2) {
#pragma unroll
    for (int v = 0; v < 2; v++) {
#pragma unroll
        for (int u = 0; u < 2; u++) {
            int j = base + 8 * u + ko + 8 * v;
            float lo = x_sh[j];
            float hi = x_sh[j + 1];
            uint32_t p1 = cvt_f16x2(hi, lo);
            float qlo, qhi;
            unpack_f16x2(p1, qlo, qhi);
            uint32_t p2 = cvt_f16x2(hi - qhi, lo - qlo);
            int r = v * 2 + u;          // a0=(u0,v0) a1=(u1,v0) a2=(u0,v1) a3=(u1,v1)
            A1[r] = p1;
            A2[r] = p2;
        }
    }
}

// ---------------------------------------------------------------------------
// Precompute: fp32 Gabor bank (reference-rounding-matched), fp16,
// scattered directly into B-fragment layout.
// ---------------------------------------------------------------------------
__global__ void gabor_precompute_kernel(const float* __restrict__ kV,
                                        const float* __restrict__ sV) {
    int idx = blockIdx.x * blockDim.x + threadIdx.x;    // 65536 = w*256 + f
    if (idx >= W_WIN * NFILT) return;
    int w = idx >> 8;
    int f = idx & 255;
    float k = kV[f];
    float s = sV[f];

    const float c0 = (float)(-2.0 * PI_D / (double)W_WIN);
    float a  = __fmul_rn(c0, k);
    float ph = __fmul_rn(a, (float)w);

    float nm     = (float)w - 128.0f;
    float inv2s2 = 1.0f / (2.0f * s * s);
    float coef   = 1.0f / sqrtf(2.0f * (float)PI_D * s * s);
    float arg    = __fmul_rn(inv2s2, __fmul_rn(nm, nm));
    float g      = __fmul_rn(coef, (float)exp(-(double)arg));

    float fr = __fmul_rn((float)cos((double)ph), g);
    float fi = __fmul_rn((float)sin((double)ph), g);

    int c = f >> 5, j = f & 31;
    int q = w >> 4, kk = w & 15;
    __half* bh = (__half*)g_bfrag;

#pragma unroll
    for (int im = 0; im < 2; im++) {
        float val = im ? fi : fr;
        int n    = 2 * j + im;
        int nt   = n >> 3;
        int lane = ((n & 7) << 2) | ((kk >> 1) & 3);
        int i4   = nt >> 1;
        int reg  = ((nt & 1) << 1) | (kk >> 3);
        int half = kk & 1;
        int u32i = (((c * 16 + q) * 4 + i4) * 32 + lane) * 4 + reg;
        bh[u32i * 2 + half] = __float2half(val);
    }
}

// ---------------------------------------------------------------------------
// Main kernel: CTA = 1024 t-rows of one (b,c), processed as 4 blocks of 256.
// 8 warps, warp tile m32 x n64. B frags loaded once per CTA (32 KB).
// SMEM: B frags 32KB | x window (512 f + pad)
// ---------------------------------------------------------------------------
#define OFF_XS   32768
#define SMEM_TOT (32768 + 2304)

__global__ void __launch_bounds__(256, 2)
wavelet_mma_kernel(const float* __restrict__ x, float* __restrict__ out) {
    extern __shared__ unsigned char smem[];
    const uint4* __restrict__ bsm = (const uint4*)smem;   // uint4 idx = (q*4+i4)*32 + lane
    float* x_sh = (float*)(smem + OFF_XS);

    const int tid  = threadIdx.x;
    const int wi   = tid >> 5;
    const int lane = tid & 31;
    const int c    = blockIdx.y;
    const int b    = blockIdx.z;
    const int t0   = blockIdx.x * ROWS_CTA;

    // Copy this channel's fragment bank (8192 u32 = 2048 uint4), coalesced.
    {
        const uint4* src = (const uint4*)(g_bfrag + c * 8192);
        uint4* dst = (uint4*)smem;
#pragma unroll
        for (int i = 0; i < 8; i++)
            dst[tid + i * 256] = src[tid + i * 256];
    }

    const int base0 = wi * 32 + (lane >> 2);
    const int ko    = (lane & 3) * 2;

    for (int blk = 0; blk < ROWS_CTA / BLK_ROWS; blk++) {
        const int tb = t0 + blk * BLK_ROWS;

        // x window: x_sh[j] = x[b, tb-128+j, c], zero-padded. 511 used.
        __syncthreads();
        for (int j = tid; j < 512; j += 256) {
            int t = tb - 128 + j;
            float v = 0.0f;
            if (t >= 0 && t < T_LEN)
                v = x[((size_t)b * T_LEN + t) * C_CH + c];
            x_sh[j] = v;
        }
        __syncthreads();

        float acc[2][8][4];
#pragma unroll
        for (int mt = 0; mt < 2; mt++)
#pragma unroll
            for (int nt = 0; nt < 8; nt++)
#pragma unroll
                for (int r = 0; r < 4; r++) acc[mt][nt][r] = 0.0f;

        uint32_t A1p[4], A2p[4], A1n[4], A2n[4];
        build_frag(x_sh, base0, ko, A1p, A2p);

#pragma unroll 4
        for (int q = 0; q < 16; q++) {
            build_frag(x_sh, base0 + (q + 1) * 16, ko, A1n, A2n);

            uint32_t bb[16];
#pragma unroll
            for (int i4 = 0; i4 < 4; i4++)
                *(uint4*)(bb + i4 * 4) = bsm[(q * 4 + i4) * 32 + lane];
#pragma unroll
            for (int nt = 0; nt < 8; nt++) {
                uint32_t b0 = bb[(nt >> 1) * 4 + (nt & 1) * 2];
                uint32_t b1 = bb[(nt >> 1) * 4 + (nt & 1) * 2 + 1];
                mma_f16(acc[0][nt], A1p, b0, b1);
                mma_f16(acc[1][nt], A1n, b0, b1);
                mma_f16(acc[0][nt], A2p, b0, b1);
                mma_f16(acc[1][nt], A2n, b0, b1);
            }

#pragma unroll
            for (int r = 0; r < 4; r++) {
                A1p[r] = A1n[r];
                A2p[r] = A2n[r];
            }
        }

        // Epilogue: power = re^2 + im^2 (re/im are the c0/c1 pair of each frag)
#pragma unroll
        for (int mt = 0; mt < 2; mt++) {
#pragma unroll
            for (int u = 0; u < 2; u++) {
                int t = tb + wi * 32 + mt * 16 + (lane >> 2) + 8 * u;
                size_t ob = ((size_t)b * T_LEN + t) * (size_t)(C_CH * R_OUT) + c * R_OUT;
#pragma unroll
                for (int nt = 0; nt < 8; nt++) {
                    float re = acc[mt][nt][2 * u];
                    float im = acc[mt][nt][2 * u + 1];
                    float p = re * re + im * im;
                    int jj = nt * 4 + (lane & 3);
                    out[ob + 31 - jj] = p;
                }
            }
        }
    }
}

// ---------------------------------------------------------------------------
// Launch
// ---------------------------------------------------------------------------
extern "C" void kernel_launch(void* const* d_in, const int* in_sizes, int n_in,
                              void* d_out, int out_size) {
    const float* x  = (const float*)d_in[0];
    const float* kV = (const float*)d_in[1];
    const float* sV = (const float*)d_in[2];
    float* out = (float*)d_out;

    const int B = in_sizes[0] / (T_LEN * C_CH);

    gabor_precompute_kernel<<<(W_WIN * NFILT + 255) / 256, 256>>>(kV, sV);

    static bool attr_set = false;
    if (!attr_set) {
        cudaFuncSetAttribute(wavelet_mma_kernel,
                             cudaFuncAttributeMaxDynamicSharedMemorySize, SMEM_TOT);
        attr_set = true;
    }

    dim3 grid(T_LEN / ROWS_CTA, C_CH, B);
    wavelet_mma_kernel<<<grid, 256, SMEM_TOT>>>(x, out);
}

// round 13
// speedup vs baseline: 3.5914x; 1.0160x over previous
#include <cuda_runtime.h>
#include <cuda_fp16.h>
#include <math.h>
#include <stdint.h>

#define T_LEN    16384
#define C_CH     8
#define W_WIN    256
#define R_OUT    32
#define NFILT    256
#define ROWS_CTA 1024
#define BLK_ROWS 256
#define XWIN     576
#define PI_D     3.14159265358979323846

// Gabor bank (fp16) pre-laid-out in m16n8k16 B-fragment order:
// u32 index = (((c*16 + q)*4 + i4)*32 + lane)*4 + reg   (256 KB, L2-resident)
__device__ uint32_t g_bfrag[65536];

// ---------------------------------------------------------------------------
// helpers
// ---------------------------------------------------------------------------
__device__ __forceinline__ uint32_t cvt_f16x2(float hi, float lo) {
    uint32_t d;
    asm("cvt.rn.f16x2.f32 %0, %1, %2;" : "=r"(d) : "f"(hi), "f"(lo));
    return d;
}
__device__ __forceinline__ void unpack_f16x2(uint32_t v, float& lo, float& hi) {
    asm("{ .reg .f16 l, h;\n\t"
        "  mov.b32 {l, h}, %2;\n\t"
        "  cvt.f32.f16 %0, l;\n\t"
        "  cvt.f32.f16 %1, h; }"
        : "=f"(lo), "=f"(hi) : "r"(v));
}

__device__ __forceinline__ void mma_f16(float* c, const uint32_t* a,
                                        uint32_t b0, uint32_t b1) {
    asm volatile(
        "mma.sync.aligned.m16n8k16.row.col.f32.f16.f16.f32 "
        "{%0,%1,%2,%3}, {%4,%5,%6,%7}, {%8,%9}, {%0,%1,%2,%3};"
        : "+f"(c[0]), "+f"(c[1]), "+f"(c[2]), "+f"(c[3])
        : "r"(a[0]), "r"(a[1]), "r"(a[2]), "r"(a[3]), "r"(b0), "r"(b1));
}

// Build A fragment pair (fp16 main + fp16 residual) for one diagonal.
// A[m,k] = x_sh[m+k]; fragment depends only on s = mt + q.
__device__ __forceinline__ void build_frag(const float* __restrict__ x_sh,
                                           int base, int ko,
                                           uint32_t* A1, uint32_t* A2) {
#pragma unroll
    for (int v = 0; v < 2; v++) {
#pragma unroll
        for (int u = 0; u < 2; u++) {
            int j = base + 8 * u + ko + 8 * v;
            float lo = x_sh[j];
            float hi = x_sh[j + 1];
            uint32_t p1 = cvt_f16x2(hi, lo);
            float qlo, qhi;
            unpack_f16x2(p1, qlo, qhi);
            uint32_t p2 = cvt_f16x2(hi - qhi, lo - qlo);
            int r = v * 2 + u;          // a0=(u0,v0) a1=(u1,v0) a2=(u0,v1) a3=(u1,v1)
            A1[r] = p1;
            A2[r] = p2;
        }
    }
}

// ---------------------------------------------------------------------------
// Precompute: fp32 Gabor bank (reference-rounding-matched), fp16,
// scattered directly into B-fragment layout.
// ---------------------------------------------------------------------------
__global__ void gabor_precompute_kernel(const float* __restrict__ kV,
                                        const float* __restrict__ sV) {
    int idx = blockIdx.x * blockDim.x + threadIdx.x;    // 65536 = w*256 + f
    if (idx >= W_WIN * NFILT) return;
    int w = idx >> 8;
    int f = idx & 255;
    float k = kV[f];
    float s = sV[f];

    const float c0 = (float)(-2.0 * PI_D / (double)W_WIN);
    float a  = __fmul_rn(c0, k);
    float ph = __fmul_rn(a, (float)w);

    float nm     = (float)w - 128.0f;
    float inv2s2 = 1.0f / (2.0f * s * s);
    float coef   = 1.0f / sqrtf(2.0f * (float)PI_D * s * s);
    float arg    = __fmul_rn(inv2s2, __fmul_rn(nm, nm));
    float g      = __fmul_rn(coef, (float)exp(-(double)arg));

    float fr = __fmul_rn((float)cos((double)ph), g);
    float fi = __fmul_rn((float)sin((double)ph), g);

    int c = f >> 5, j = f & 31;
    int q = w >> 4, kk = w & 15;
    __half* bh = (__half*)g_bfrag;

#pragma unroll
    for (int im = 0; im < 2; im++) {
        float val = im ? fi : fr;
        int n    = 2 * j + im;
        int nt   = n >> 3;
        int lane = ((n & 7) << 2) | ((kk >> 1) & 3);
        int i4   = nt >> 1;
        int reg  = ((nt & 1) << 1) | (kk >> 3);
        int half = kk & 1;
        int u32i = (((c * 16 + q) * 4 + i4) * 32 + lane) * 4 + reg;
        bh[u32i * 2 + half] = __float2half(val);
    }
}

// ---------------------------------------------------------------------------
// Main kernel: CTA = 1024 t-rows of one (b,c), processed as 4 blocks of 256.
// 8 warps, warp tile m32 x n64. B frags loaded once per CTA (32 KB).
// Depth-2 A-frag pipeline; double-buffered x windows.
// SMEM: B frags 32KB | 2 x 576-float x windows
// ---------------------------------------------------------------------------
#define OFF_XS   32768
#define SMEM_TOT (32768 + 2 * XWIN * 4)

__global__ void __launch_bounds__(256, 2)
wavelet_mma_kernel(const float* __restrict__ x, float* __restrict__ out) {
    extern __shared__ unsigned char smem[];
    const uint4* __restrict__ bsm = (const uint4*)smem;   // uint4 idx = (q*4+i4)*32 + lane
    float* xbuf = (float*)(smem + OFF_XS);

    const int tid  = threadIdx.x;
    const int wi   = tid >> 5;
    const int lane = tid & 31;
    const int c    = blockIdx.y;
    const int b    = blockIdx.z;
    const int t0   = blockIdx.x * ROWS_CTA;
    const size_t xrow = (size_t)b * T_LEN;

    // Copy this channel's fragment bank (8192 u32 = 2048 uint4), coalesced.
    {
        const uint4* src = (const uint4*)(g_bfrag + c * 8192);
        uint4* dst = (uint4*)smem;
#pragma unroll
        for (int i = 0; i < 8; i++)
            dst[tid + i * 256] = src[tid + i * 256];
    }

    // Window for blk 0: xbuf[j] = x[b, t0-128+j, c], zero-padded.
    for (int j = tid; j < XWIN; j += 256) {
        int t = t0 - 128 + j;
        float v = 0.0f;
        if (t >= 0 && t < T_LEN)
            v = x[(xrow + t) * C_CH + c];
        xbuf[j] = v;
    }
    __syncthreads();

    const int base0 = wi * 32 + (lane >> 2);
    const int ko    = (lane & 3) * 2;
    const int NBLK  = ROWS_CTA / BLK_ROWS;

    for (int blk = 0; blk < NBLK; blk++) {
        const int tb = t0 + blk * BLK_ROWS;
        const float* xcur = xbuf + (blk & 1) * XWIN;
        float* xnxt = xbuf + ((blk + 1) & 1) * XWIN;

        // Prefetch next blk's window into registers (hidden under q-loop).
        float v0 = 0.0f, v1 = 0.0f, v2 = 0.0f;
        const bool have_next = (blk + 1 < NBLK);
        if (have_next) {
            const int tbn = tb + BLK_ROWS - 128;
            int t = tbn + tid;
            if (t < T_LEN) v0 = x[(xrow + t) * C_CH + c];
            t = tbn + tid + 256;
            if (t < T_LEN) v1 = x[(xrow + t) * C_CH + c];
            if (tid < XWIN - 512) {
                t = tbn + tid + 512;
                if (t < T_LEN) v2 = x[(xrow + t) * C_CH + c];
            }
        }

        float acc[2][8][4];
#pragma unroll
        for (int mt = 0; mt < 2; mt++)
#pragma unroll
            for (int nt = 0; nt < 8; nt++)
#pragma unroll
                for (int r = 0; r < 4; r++) acc[mt][nt][r] = 0.0f;

        // Pipeline prologue: frags for diagonals 0 and 1.
        uint32_t P1[4], P2[4], N1[4], N2[4], T1[4], T2[4];
        build_frag(xcur, base0, ko, P1, P2);
        build_frag(xcur, base0 + 16, ko, N1, N2);

#pragma unroll 4
        for (int q = 0; q < 16; q++) {
            uint32_t bbA[8], bbB[8];
#pragma unroll
            for (int i4 = 0; i4 < 2; i4++)
                *(uint4*)(bbA + i4 * 4) = bsm[(q * 4 + i4) * 32 + lane];

            // First nt-half (uses bbA) — no dependency on this iter's build.
#pragma unroll
            for (int nt = 0; nt < 4; nt++) {
                uint32_t b0 = bbA[(nt >> 1) * 4 + (nt & 1) * 2];
                uint32_t b1 = bbA[(nt >> 1) * 4 + (nt & 1) * 2 + 1];
                mma_f16(acc[0][nt], P1, b0, b1);
                mma_f16(acc[1][nt], N1, b0, b1);
                mma_f16(acc[0][nt], P2, b0, b1);
                mma_f16(acc[1][nt], N2, b0, b1);
            }

            // Build diagonal q+2 — consumed only next iteration (full slack).
            // Over-reads diag 17 on q=15 stay inside the 576-entry window
            // and are never consumed.
            build_frag(xcur, base0 + (q + 2) * 16, ko, T1, T2);

#pragma unroll
            for (int i4 = 0; i4 < 2; i4++)
                *(uint4*)(bbB + i4 * 4) = bsm[(q * 4 + 2 + i4) * 32 + lane];

            // Second nt-half (uses bbB).
#pragma unroll
            for (int nt = 4; nt < 8; nt++) {
                uint32_t b0 = bbB[((nt - 4) >> 1) * 4 + (nt & 1) * 2];
                uint32_t b1 = bbB[((nt - 4) >> 1) * 4 + (nt & 1) * 2 + 1];
                mma_f16(acc[0][nt], P1, b0, b1);
                mma_f16(acc[1][nt], N1, b0, b1);
                mma_f16(acc[0][nt], P2, b0, b1);
                mma_f16(acc[1][nt], N2, b0, b1);
            }

            // Rotate pipeline.
#pragma unroll
            for (int r = 0; r < 4; r++) {
                P1[r] = N1[r];  P2[r] = N2[r];
                N1[r] = T1[r];  N2[r] = T2[r];
            }
        }

        // Epilogue: power = re^2 + im^2 (re/im are the c0/c1 pair of each frag)
#pragma unroll
        for (int mt = 0; mt < 2; mt++) {
#pragma unroll
            for (int u = 0; u < 2; u++) {
                int t = tb + wi * 32 + mt * 16 + (lane >> 2) + 8 * u;
                size_t ob = (xrow + t) * (size_t)(C_CH * R_OUT) + c * R_OUT;
#pragma unroll
                for (int nt = 0; nt < 8; nt++) {
                    float re = acc[mt][nt][2 * u];
                    float im = acc[mt][nt][2 * u + 1];
                    float p = re * re + im * im;
                    int jj = nt * 4 + (lane & 3);
                    out[ob + 31 - jj] = p;
                }
            }
        }

        // Publish next window.
        if (have_next) {
            xnxt[tid]       = v0;
            xnxt[tid + 256] = v1;
            if (tid < XWIN - 512) xnxt[tid + 512] = v2;
        }
        __syncthreads();
    }
}

// ---------------------------------------------------------------------------
// Launch
// ---------------------------------------------------------------------------
extern "C" void kernel_launch(void* const* d_in, const int* in_sizes, int n_in,
                              void* d_out, int out_size) {
    const float* x  = (const float*)d_in[0];
    const float* kV = (const float*)d_in[1];
    const float* sV = (const float*)d_in[2];
    float* out = (float*)d_out;

    const int B = in_sizes[0] / (T_LEN * C_CH);

    gabor_precompute_kernel<<<(W_WIN * NFILT + 255) / 256, 256>>>(kV, sV);

    static bool attr_set = false;
    if (!attr_set) {
        cudaFuncSetAttribute(wavelet_mma_kernel,
                             cudaFuncAttributeMaxDynamicSharedMemorySize, SMEM_TOT);
        attr_set = true;
    }

    dim3 grid(T_LEN / ROWS_CTA, C_CH, B);
    wavelet_mma_kernel<<<grid, 256, SMEM_TOT>>>(x, out);
}

// round 16
// speedup vs baseline: 5.5440x; 1.5437x over previous
#include <cuda_runtime.h>
#include <cuda_fp16.h>
#include <math.h>
#include <stdint.h>

#define T_LEN    16384
#define C_CH     8
#define W_WIN    256
#define R_OUT    32
#define NFILT    256
#define ROWS_CTA 1024
#define BLK_ROWS 256
#define XWIN     576
#define PI_D     3.14159265358979323846

// Gabor bank (fp16) pre-laid-out in m16n8k16 B-fragment order:
// u32 index = (((c*16 + q)*4 + i4)*32 + lane)*4 + reg   (256 KB, L2-resident)
__device__ uint32_t g_bfrag[65536];

// ---------------------------------------------------------------------------
// helpers
// ---------------------------------------------------------------------------
__device__ __forceinline__ uint32_t cvt_f16x2(float hi, float lo) {
    uint32_t d;
    asm("cvt.rn.f16x2.f32 %0, %1, %2;" : "=r"(d) : "f"(hi), "f"(lo));
    return d;
}

__device__ __forceinline__ void mma_f16(float* c, const uint32_t* a,
                                        uint32_t b0, uint32_t b1) {
    asm volatile(
        "mma.sync.aligned.m16n8k16.row.col.f32.f16.f16.f32 "
        "{%0,%1,%2,%3}, {%4,%5,%6,%7}, {%8,%9}, {%0,%1,%2,%3};"
        : "+f"(c[0]), "+f"(c[1]), "+f"(c[2]), "+f"(c[3])
        : "r"(a[0]), "r"(a[1]), "r"(a[2]), "r"(a[3]), "r"(b0), "r"(b1));
}

// Build A fragment (fp16) for one diagonal. A[m,k] = x_sh[m+k];
// fragment depends only on s = mt + q.
__device__ __forceinline__ void build_frag(const float* __restrict__ x_sh,
                                           int base, int ko, uint32_t* A1) {
#pragma unroll
    for (int v = 0; v < 2; v++) {
#pragma unroll
        for (int u = 0; u < 2; u++) {
            int j = base + 8 * u + ko + 8 * v;
            float lo = x_sh[j];
            float hi = x_sh[j + 1];
            A1[v * 2 + u] = cvt_f16x2(hi, lo);  // a0=(u0,v0) a1=(u1,v0) a2=(u0,v1) a3=(u1,v1)
        }
    }
}

// ---------------------------------------------------------------------------
// Precompute: fp32 Gabor bank (reference-rounding-matched), fp16,
// scattered directly into B-fragment layout.
// ---------------------------------------------------------------------------
__global__ void gabor_precompute_kernel(const float* __restrict__ kV,
                                        const float* __restrict__ sV) {
    int idx = blockIdx.x * blockDim.x + threadIdx.x;    // 65536 = w*256 + f
    if (idx >= W_WIN * NFILT) return;
    int w = idx >> 8;
    int f = idx & 255;
    float k = kV[f];
    float s = sV[f];

    const float c0 = (float)(-2.0 * PI_D / (double)W_WIN);
    float a  = __fmul_rn(c0, k);
    float ph = __fmul_rn(a, (float)w);

    float nm     = (float)w - 128.0f;
    float inv2s2 = 1.0f / (2.0f * s * s);
    float coef   = 1.0f / sqrtf(2.0f * (float)PI_D * s * s);
    float arg    = __fmul_rn(inv2s2, __fmul_rn(nm, nm));
    float g      = __fmul_rn(coef, (float)exp(-(double)arg));

    float fr = __fmul_rn((float)cos((double)ph), g);
    float fi = __fmul_rn((float)sin((double)ph), g);

    int c = f >> 5, j = f & 31;
    int q = w >> 4, kk = w & 15;
    __half* bh = (__half*)g_bfrag;

#pragma unroll
    for (int im = 0; im < 2; im++) {
        float val = im ? fi : fr;
        int n    = 2 * j + im;
        int nt   = n >> 3;
        int lane = ((n & 7) << 2) | ((kk >> 1) & 3);
        int i4   = nt >> 1;
        int reg  = ((nt & 1) << 1) | (kk >> 3);
        int half = kk & 1;
        int u32i = (((c * 16 + q) * 4 + i4) * 32 + lane) * 4 + reg;
        bh[u32i * 2 + half] = __float2half(val);
    }
}

// ---------------------------------------------------------------------------
// Main kernel: CTA = 1024 t-rows of one (b,c), processed as 4 blocks of 256.
// 8 warps, warp tile m32 x n64, single fp16 pass (16 MMA / q-step).
// B frags loaded once per CTA (32 KB). Depth-2 A-frag pipeline;
// double-buffered x windows.
// SMEM: B frags 32KB | 2 x 576-float x windows
// ---------------------------------------------------------------------------
#define OFF_XS   32768
#define SMEM_TOT (32768 + 2 * XWIN * 4)

__global__ void __launch_bounds__(256, 2)
wavelet_mma_kernel(const float* __restrict__ x, float* __restrict__ out) {
    extern __shared__ unsigned char smem[];
    const uint4* __restrict__ bsm = (const uint4*)smem;   // uint4 idx = (q*4+i4)*32 + lane
    float* xbuf = (float*)(smem + OFF_XS);

    const int tid  = threadIdx.x;
    const int wi   = tid >> 5;
    const int lane = tid & 31;
    const int c    = blockIdx.y;
    const int b    = blockIdx.z;
    const int t0   = blockIdx.x * ROWS_CTA;
    const size_t xrow = (size_t)b * T_LEN;

    // Copy this channel's fragment bank (8192 u32 = 2048 uint4), coalesced.
    {
        const uint4* src = (const uint4*)(g_bfrag + c * 8192);
        uint4* dst = (uint4*)smem;
#pragma unroll
        for (int i = 0; i < 8; i++)
            dst[tid + i * 256] = src[tid + i * 256];
    }

    // Window for blk 0: xbuf[j] = x[b, t0-128+j, c], zero-padded.
    for (int j = tid; j < XWIN; j += 256) {
        int t = t0 - 128 + j;
        float v = 0.0f;
        if (t >= 0 && t < T_LEN)
            v = x[(xrow + t) * C_CH + c];
        xbuf[j] = v;
    }
    __syncthreads();

    const int base0 = wi * 32 + (lane >> 2);
    const int ko    = (lane & 3) * 2;
    const int NBLK  = ROWS_CTA / BLK_ROWS;

    for (int blk = 0; blk < NBLK; blk++) {
        const int tb = t0 + blk * BLK_ROWS;
        const float* xcur = xbuf + (blk & 1) * XWIN;
        float* xnxt = xbuf + ((blk + 1) & 1) * XWIN;

        // Prefetch next blk's window into registers (hidden under q-loop).
        float v0 = 0.0f, v1 = 0.0f, v2 = 0.0f;
        const bool have_next = (blk + 1 < NBLK);
        if (have_next) {
            const int tbn = tb + BLK_ROWS - 128;
            int t = tbn + tid;
            if (t < T_LEN) v0 = x[(xrow + t) * C_CH + c];
            t = tbn + tid + 256;
            if (t < T_LEN) v1 = x[(xrow + t) * C_CH + c];
            if (tid < XWIN - 512) {
                t = tbn + tid + 512;
                if (t < T_LEN) v2 = x[(xrow + t) * C_CH + c];
            }
        }

        float acc[2][8][4];
#pragma unroll
        for (int mt = 0; mt < 2; mt++)
#pragma unroll
            for (int nt = 0; nt < 8; nt++)
#pragma unroll
                for (int r = 0; r < 4; r++) acc[mt][nt][r] = 0.0f;

        // Pipeline prologue: frags for diagonals 0 and 1.
        uint32_t P1[4], N1[4], T1[4];
        build_frag(xcur, base0, ko, P1);
        build_frag(xcur, base0 + 16, ko, N1);

#pragma unroll 4
        for (int q = 0; q < 16; q++) {
            uint32_t bbA[8], bbB[8];
#pragma unroll
            for (int i4 = 0; i4 < 2; i4++)
                *(uint4*)(bbA + i4 * 4) = bsm[(q * 4 + i4) * 32 + lane];

            // First nt-half (uses bbA) — no dependency on this iter's build.
#pragma unroll
            for (int nt = 0; nt < 4; nt++) {
                uint32_t b0 = bbA[(nt >> 1) * 4 + (nt & 1) * 2];
                uint32_t b1 = bbA[(nt >> 1) * 4 + (nt & 1) * 2 + 1];
                mma_f16(acc[0][nt], P1, b0, b1);
                mma_f16(acc[1][nt], N1, b0, b1);
            }

            // Build diagonal q+2 — consumed only next iteration (full slack).
            // Over-reads of diag 17 on q=15 stay inside the 576-entry window
            // and are never consumed.
            build_frag(xcur, base0 + (q + 2) * 16, ko, T1);

#pragma unroll
            for (int i4 = 0; i4 < 2; i4++)
                *(uint4*)(bbB + i4 * 4) = bsm[(q * 4 + 2 + i4) * 32 + lane];

            // Second nt-half (uses bbB).
#pragma unroll
            for (int nt = 4; nt < 8; nt++) {
                uint32_t b0 = bbB[((nt - 4) >> 1) * 4 + (nt & 1) * 2];
                uint32_t b1 = bbB[((nt - 4) >> 1) * 4 + (nt & 1) * 2 + 1];
                mma_f16(acc[0][nt], P1, b0, b1);
                mma_f16(acc[1][nt], N1, b0, b1);
            }

            // Rotate pipeline.
#pragma unroll
            for (int r = 0; r < 4; r++) {
                P1[r] = N1[r];
                N1[r] = T1[r];
            }
        }

        // Epilogue: power = re^2 + im^2 (re/im are the c0/c1 pair of each frag)
#pragma unroll
        for (int mt = 0; mt < 2; mt++) {
#pragma unroll
            for (int u = 0; u < 2; u++) {
                int t = tb + wi * 32 + mt * 16 + (lane >> 2) + 8 * u;
                size_t ob = (xrow + t) * (size_t)(C_CH * R_OUT) + c * R_OUT;
#pragma unroll
                for (int nt = 0; nt < 8; nt++) {
                    float re = acc[mt][nt][2 * u];
                    float im = acc[mt][nt][2 * u + 1];
                    float p = re * re + im * im;
                    int jj = nt * 4 + (lane & 3);
                    out[ob + 31 - jj] = p;
                }
            }
        }

        // Publish next window.
        if (have_next) {
            xnxt[tid]       = v0;
            xnxt[tid + 256] = v1;
            if (tid < XWIN - 512) xnxt[tid + 512] = v2;
        }
        __syncthreads();
    }
}

// ---------------------------------------------------------------------------
// Launch
// ---------------------------------------------------------------------------
extern "C" void kernel_launch(void* const* d_in, const int* in_sizes, int n_in,
                              void* d_out, int out_size) {
    const float* x  = (const float*)d_in[0];
    const float* kV = (const float*)d_in[1];
    const float* sV = (const float*)d_in[2];
    float* out = (float*)d_out;

    const int B = in_sizes[0] / (T_LEN * C_CH);

    gabor_precompute_kernel<<<(W_WIN * NFILT + 255) / 256, 256>>>(kV, sV);

    static bool attr_set = false;
    if (!attr_set) {
        cudaFuncSetAttribute(wavelet_mma_kernel,
                             cudaFuncAttributeMaxDynamicSharedMemorySize, SMEM_TOT);
        attr_set = true;
    }

    dim3 grid(T_LEN / ROWS_CTA, C_CH, B);
    wavelet_mma_kernel<<<grid, 256, SMEM_TOT>>>(x, out);
}